// round 5
// baseline (speedup 1.0000x reference)
#include <cuda_runtime.h>
#include <cstdint>
#include <cstddef>

// ---------------- problem constants ----------------
#define NTOKENS 8192
#define TOPK    2
#define NEXP    8
#define KDIM    1024
#define NDIM    1024
#define M_OUT   (NTOKENS * TOPK)          // 16384 dispatched rows

#define TILE_M  128
#define TILE_N  256
#define CHUNK_K 32                        // fp32/tf32 elems per K chunk
#define NUM_CHUNKS (KDIM / CHUNK_K)       // 32
#define N_TILES (NDIM / TILE_N)           // 4
#define MAX_ROW_TILES 136                 // 16384/128 + NEXP slack
#define THREADS 512
#define STAGES  3

// smem: padded row stride 36 floats (144B) -> conflict-free fragment loads
#define A_STRIDE 36
#define B_STRIDE 36
#define A_STAGE_BYTES (TILE_M * A_STRIDE * 4)   // 18432
#define B_STAGE_BYTES (TILE_N * B_STRIDE * 4)   // 36864
#define STAGE_BYTES   (A_STAGE_BYTES + B_STAGE_BYTES)  // 55296
#define SM_TOK   0                               // 128 ints
#define SM_STAGE0 1024
#define SMEM_ALLOC (SM_STAGE0 + STAGES * STAGE_BYTES)  // 166912

// ---------------- PTX helpers (base sm_80+ ISA; harness targets sm_103 base) -
__device__ __forceinline__ uint32_t smem_to_u32(const void* p) {
    uint32_t a;
    asm("{ .reg .u64 t; cvta.to.shared.u64 t, %1; cvt.u32.u64 %0, t; }" : "=r"(a) : "l"(p));
    return a;
}
#define CP_ASYNC16(dst_u32, src_ptr) \
    asm volatile("cp.async.cg.shared.global [%0], [%1], 16;" :: "r"(dst_u32), "l"(src_ptr))
#define CP_COMMIT() asm volatile("cp.async.commit_group;" ::: "memory")
#define CP_WAIT_1() asm volatile("cp.async.wait_group 1;" ::: "memory")

__device__ __forceinline__ uint32_t f2tf32(float f) {
    uint32_t r;
    asm("cvt.rna.tf32.f32 %0, %1;" : "=r"(r) : "f"(f));
    return r;
}

// mma.sync m16n8k8 tf32, fp32 accumulate (operands already tf32-rounded bits)
__device__ __forceinline__ void mma_tf32(float* c, const uint32_t* a, const uint32_t* b) {
    asm volatile(
        "mma.sync.aligned.m16n8k8.row.col.f32.tf32.tf32.f32 "
        "{%0,%1,%2,%3}, {%4,%5,%6,%7}, {%8,%9}, {%0,%1,%2,%3};"
        : "+f"(c[0]), "+f"(c[1]), "+f"(c[2]), "+f"(c[3])
        : "r"(a[0]), "r"(a[1]), "r"(a[2]), "r"(a[3]), "r"(b[0]), "r"(b[1]));
}

// ---------------- static device scratch (allocation-free rule) --------------
__device__ float g_xt[(size_t)NTOKENS * KDIM];          // tf32-rounded, k-permuted
__device__ float g_wt[(size_t)NEXP * NDIM * KDIM];      // tf32-rounded, k-permuted
__device__ int g_token_of_row[M_OUT];
__device__ int g_tile_expert[MAX_ROW_TILES];
__device__ int g_tile_row0[MAX_ROW_TILES];
__device__ int g_tile_rows[MAX_ROW_TILES];
__device__ int g_num_tiles;

// ---------------- setup kernels ---------------------------------------------
// Round to tf32 (rna) AND permute each 8-wide k group: orig col j -> 2*(j&3)+(j>>2).
// So fragment cols (c, c+4) become adjacent -> LDS.64 fragment loads in the GEMM.
__global__ void k_round(const float* __restrict__ x, const float* __restrict__ w) {
    const size_t HALF_GROUPS = (size_t)NTOKENS * KDIM / 8;   // == NEXP*NDIM*KDIM/8
    size_t g = (size_t)blockIdx.x * blockDim.x + threadIdx.x;
    const float* src;
    float* dst;
    if (g < HALF_GROUPS)          { src = x; dst = g_xt; }
    else if (g < 2 * HALF_GROUPS) { src = w; dst = g_wt; g -= HALF_GROUPS; }
    else return;
    size_t base = g * 8;
    float4 lo = *reinterpret_cast<const float4*>(src + base);
    float4 hi = *reinterpret_cast<const float4*>(src + base + 4);
    uint32_t v[8];
    v[0] = f2tf32(lo.x); v[2] = f2tf32(lo.y); v[4] = f2tf32(lo.z); v[6] = f2tf32(lo.w);
    v[1] = f2tf32(hi.x); v[3] = f2tf32(hi.y); v[5] = f2tf32(hi.z); v[7] = f2tf32(hi.w);
    *reinterpret_cast<uint4*>(dst + base)     = make_uint4(v[0], v[1], v[2], v[3]);
    *reinterpret_cast<uint4*>(dst + base + 4) = make_uint4(v[4], v[5], v[6], v[7]);
}

__global__ void k_token(const int* __restrict__ scatter) {
    int i = blockIdx.x * blockDim.x + threadIdx.x;
    if (i < M_OUT) g_token_of_row[scatter[i]] = i / TOPK;
}

__global__ void k_tiles(const int* __restrict__ splits) {
    if (threadIdx.x != 0 || blockIdx.x != 0) return;
    int off = 0, t = 0;
    for (int e = 0; e < NEXP; e++) {
        int sc = splits[e];
        for (int m0 = 0; m0 < sc; m0 += TILE_M) {
            g_tile_expert[t] = e;
            g_tile_row0[t]   = off + m0;
            int rr = sc - m0;
            g_tile_rows[t]   = rr < TILE_M ? rr : TILE_M;
            t++;
        }
        off += sc;
    }
    g_num_tiles = t;
}

// ---------------- main grouped-GEMM kernel -----------------------------------
// 16 warps: warp grid 2 (M) x 8 (N), warp tile 64x32.
__global__ void __launch_bounds__(THREADS, 1) moe_gemm_kernel(float* __restrict__ out) {
    extern __shared__ char smem[];
    const uint32_t sbase = smem_to_u32(smem);

    const int row_tile = blockIdx.x;
    if (row_tile >= g_num_tiles) return;
    const int e    = g_tile_expert[row_tile];
    const int row0 = g_tile_row0[row_tile];
    const int rows = g_tile_rows[row_tile];
    const int n0   = blockIdx.y * TILE_N;

    const int tid  = threadIdx.x;
    const int wid  = tid >> 5;
    const int lane = tid & 31;
    const int lr = lane >> 2;         // 0..7  (fragment row within 8)
    const int lc = lane & 3;          // 0..3  (fragment col group)
    const int wm = (wid >> 3) * 64;   // warp M offset (2 rows of warps)
    const int wn = (wid & 7) * 32;    // warp N offset (8 cols of warps)

    // tokens of this tile's rows (padding rows clamp to a valid token)
    int* s_tok = reinterpret_cast<int*>(smem + SM_TOK);
    if (tid < TILE_M) {
        int r = (tid < rows) ? (row0 + tid) : row0;
        s_tok[tid] = g_token_of_row[r];
    }
    __syncthreads();

    // ---- per-thread cp.async plan (constant across chunks except k offset) ----
    const int seg   = tid & 7;          // which 16B of the 128B row-chunk
    const int rbase = tid >> 3;         // 0..63
    size_t a_src[2];
    uint32_t a_dst[2];
#pragma unroll
    for (int j = 0; j < 2; j++) {
        int row = rbase + 64 * j;
        a_src[j] = (size_t)s_tok[row] * KDIM + (size_t)seg * 4;
        a_dst[j] = (uint32_t)(row * (A_STRIDE * 4) + seg * 16);
    }
    size_t b_src[4];
    uint32_t b_dst[4];
#pragma unroll
    for (int j = 0; j < 4; j++) {
        int row = rbase + 64 * j;
        b_src[j] = ((size_t)e * NDIM + n0 + row) * KDIM + (size_t)seg * 4;
        b_dst[j] = (uint32_t)(row * (B_STRIDE * 4) + seg * 16);
    }

    auto load_stage = [&](int ch, int s) {
        const uint32_t abase = sbase + SM_STAGE0 + s * STAGE_BYTES;
        const uint32_t bbase = abase + A_STAGE_BYTES;
        const size_t koff = (size_t)ch * CHUNK_K;
#pragma unroll
        for (int j = 0; j < 2; j++)
            CP_ASYNC16(abase + a_dst[j], g_xt + a_src[j] + koff);
#pragma unroll
        for (int j = 0; j < 4; j++)
            CP_ASYNC16(bbase + b_dst[j], g_wt + b_src[j] + koff);
    };

    // ---- accumulators: warp tile 64x32 -> 4 mf x 4 nf x 4 regs ----
    float acc[4][4][4];
#pragma unroll
    for (int mf = 0; mf < 4; mf++)
#pragma unroll
        for (int nf = 0; nf < 4; nf++)
#pragma unroll
            for (int r = 0; r < 4; r++) acc[mf][nf][r] = 0.f;

    // prefetch stages 0,1
    load_stage(0, 0); CP_COMMIT();
    load_stage(1, 1); CP_COMMIT();

    const float* As0 = reinterpret_cast<const float*>(smem + SM_STAGE0);

#pragma unroll 1
    for (int ch = 0; ch < NUM_CHUNKS; ch++) {
        CP_WAIT_1();                 // own groups: load(ch) landed
        __syncthreads();             // all threads' load(ch) landed; stage (ch-1)%3 drained

        // refill the stage all warps just finished reading (single-sync multistage)
        if (ch + 2 < NUM_CHUNKS) load_stage(ch + 2, (ch + 2) % STAGES);
        CP_COMMIT();

        const int s = ch % STAGES;
        const float* As = As0 + (size_t)s * (STAGE_BYTES / 4);
        const float* Bs = As + (A_STAGE_BYTES / 4);

#pragma unroll
        for (int kf = 0; kf < 4; kf++) {
            const int kcol = kf * 8 + 2 * lc;    // permuted: (c, c+4) adjacent
            uint32_t af[4][4];
#pragma unroll
            for (int mf = 0; mf < 4; mf++) {
                const int r = wm + mf * 16 + lr;
                uint2 t0 = *reinterpret_cast<const uint2*>(As + r * A_STRIDE + kcol);
                uint2 t1 = *reinterpret_cast<const uint2*>(As + (r + 8) * A_STRIDE + kcol);
                af[mf][0] = t0.x; af[mf][1] = t1.x; af[mf][2] = t0.y; af[mf][3] = t1.y;
            }
            uint32_t bf[4][2];
#pragma unroll
            for (int nf = 0; nf < 4; nf++) {
                const int r = wn + nf * 8 + lr;
                uint2 t = *reinterpret_cast<const uint2*>(Bs + r * B_STRIDE + kcol);
                bf[nf][0] = t.x; bf[nf][1] = t.y;
            }
#pragma unroll
            for (int mf = 0; mf < 4; mf++)
#pragma unroll
                for (int nf = 0; nf < 4; nf++)
                    mma_tf32(acc[mf][nf], af[mf], bf[nf]);
        }
    }

    // ---- epilogue: direct float2 stores, mask rows beyond this tile ----
#pragma unroll
    for (int mf = 0; mf < 4; mf++) {
        const int r_lo = wm + mf * 16 + lr;
        const int r_hi = r_lo + 8;
        const bool v_lo = (r_lo < rows);
        const bool v_hi = (r_hi < rows);
        float* o_lo = out + (size_t)(row0 + r_lo) * NDIM + n0;
        float* o_hi = out + (size_t)(row0 + r_hi) * NDIM + n0;
#pragma unroll
        for (int nf = 0; nf < 4; nf++) {
            const int col = wn + nf * 8 + 2 * lc;
            if (v_lo) *reinterpret_cast<float2*>(o_lo + col) =
                make_float2(acc[mf][nf][0], acc[mf][nf][1]);
            if (v_hi) *reinterpret_cast<float2*>(o_hi + col) =
                make_float2(acc[mf][nf][2], acc[mf][nf][3]);
        }
    }
}

// ---------------- launch ------------------------------------------------------
extern "C" void kernel_launch(void* const* d_in, const int* in_sizes, int n_in,
                              void* d_out, int out_size) {
    const float* x       = (const float*)d_in[0];
    const float* w       = (const float*)d_in[1];
    const int*   scatter = (const int*)d_in[2];
    const int*   splits  = (const int*)d_in[3];
    float*       out     = (float*)d_out;
    (void)in_sizes; (void)n_in; (void)out_size;

    cudaFuncSetAttribute(moe_gemm_kernel, cudaFuncAttributeMaxDynamicSharedMemorySize, SMEM_ALLOC);

    const size_t total_groups = ((size_t)NTOKENS * KDIM + (size_t)NEXP * NDIM * KDIM) / 8;
    k_round<<<(int)((total_groups + 255) / 256), 256>>>(x, w);
    k_token<<<(M_OUT + 255) / 256, 256>>>(scatter);
    k_tiles<<<1, 32>>>(splits);

    dim3 grid(MAX_ROW_TILES, N_TILES);
    moe_gemm_kernel<<<grid, THREADS, SMEM_ALLOC>>>(out);
}

// round 7
// speedup vs baseline: 1.2405x; 1.2405x over previous
#include <cuda_runtime.h>
#include <cstdint>
#include <cstddef>

// ---------------- problem constants ----------------
#define NTOKENS 8192
#define TOPK    2
#define NEXP    8
#define KDIM    1024
#define NDIM    1024
#define M_OUT   (NTOKENS * TOPK)          // 16384 dispatched rows

#define TILE_M  128
#define TILE_N  128
#define CHUNK_K 32                        // fp32/tf32 elems per K chunk
#define NUM_CHUNKS (KDIM / CHUNK_K)       // 32
#define N_TILES (NDIM / TILE_N)           // 8
#define MAX_ROW_TILES 136                 // 16384/128 + NEXP slack
#define THREADS 128
#define STAGES  3

// smem: padded row stride 36 floats (144B) -> conflict-free LDS.128 fragments
#define A_STRIDE 36
#define B_STRIDE 36
#define A_STAGE_BYTES (TILE_M * A_STRIDE * 4)   // 18432
#define B_STAGE_BYTES (TILE_N * B_STRIDE * 4)   // 18432
#define STAGE_BYTES   (A_STAGE_BYTES + B_STAGE_BYTES)  // 36864
#define SM_TOK    0                              // 128 ints
#define SM_STAGE0 512
#define SMEM_ALLOC (SM_STAGE0 + STAGES * STAGE_BYTES)  // 111104 -> 2 CTAs/SM

// ---------------- PTX helpers (base sm_80+ ISA; harness targets sm_103 base) -
__device__ __forceinline__ uint32_t smem_to_u32(const void* p) {
    uint32_t a;
    asm("{ .reg .u64 t; cvta.to.shared.u64 t, %1; cvt.u32.u64 %0, t; }" : "=r"(a) : "l"(p));
    return a;
}
#define CP_ASYNC16(dst_u32, src_ptr) \
    asm volatile("cp.async.cg.shared.global [%0], [%1], 16;" :: "r"(dst_u32), "l"(src_ptr))
#define CP_COMMIT() asm volatile("cp.async.commit_group;" ::: "memory")
#define CP_WAIT_1() asm volatile("cp.async.wait_group 1;" ::: "memory")

__device__ __forceinline__ uint32_t f2tf32(float f) {
    uint32_t r;
    asm("cvt.rna.tf32.f32 %0, %1;" : "=r"(r) : "f"(f));
    return r;
}

// mma.sync m16n8k8 tf32, fp32 accumulate (operands already tf32-rounded bits)
__device__ __forceinline__ void mma_tf32(float* c, uint32_t a0, uint32_t a1, uint32_t a2,
                                         uint32_t a3, uint32_t b0, uint32_t b1) {
    asm volatile(
        "mma.sync.aligned.m16n8k8.row.col.f32.tf32.tf32.f32 "
        "{%0,%1,%2,%3}, {%4,%5,%6,%7}, {%8,%9}, {%0,%1,%2,%3};"
        : "+f"(c[0]), "+f"(c[1]), "+f"(c[2]), "+f"(c[3])
        : "r"(a0), "r"(a1), "r"(a2), "r"(a3), "r"(b0), "r"(b1));
}

// ---------------- static device scratch (allocation-free rule) --------------
__device__ float g_xt[(size_t)NTOKENS * KDIM];          // tf32-rounded, packed
__device__ float g_wt[(size_t)NEXP * NDIM * KDIM];      // tf32-rounded, packed
__device__ int g_token_of_row[M_OUT];
__device__ int g_tile_expert[MAX_ROW_TILES];
__device__ int g_tile_row0[MAX_ROW_TILES];
__device__ int g_tile_rows[MAX_ROW_TILES];
__device__ int g_num_tiles;

// ---------------- setup kernels ---------------------------------------------
// tf32-round (rna) and repack each aligned 32-float k-chunk so that for each
// lc (0..3) the four kf fragment PAIRS are contiguous:
//   dst pos p = 8*lc + 2*kf + pair  <-  src j = kf*8 + lc + 4*pair
// => one LDS.128 in the GEMM fetches both k-pairs of a kf-pair for one lc.
__global__ void k_round(const float* __restrict__ x, const float* __restrict__ w) {
    const size_t HALF_CHUNKS = (size_t)NTOKENS * KDIM / 32;   // == NEXP*NDIM*KDIM/32
    size_t g = (size_t)blockIdx.x * blockDim.x + threadIdx.x;
    const float* src;
    float* dst;
    if (g < HALF_CHUNKS)          { src = x; dst = g_xt; }
    else if (g < 2 * HALF_CHUNKS) { src = w; dst = g_wt; g -= HALF_CHUNKS; }
    else return;
    const size_t base = g * 32;
    float v[32];
#pragma unroll
    for (int q = 0; q < 8; q++)
        *reinterpret_cast<float4*>(v + q * 4) = *reinterpret_cast<const float4*>(src + base + q * 4);
    uint32_t o[32];
#pragma unroll
    for (int p = 0; p < 32; p++) {
        const int lc = p >> 3, kf = (p & 7) >> 1, pair = p & 1;
        o[p] = f2tf32(v[kf * 8 + lc + 4 * pair]);
    }
#pragma unroll
    for (int q = 0; q < 8; q++)
        *reinterpret_cast<uint4*>(dst + base + q * 4) =
            make_uint4(o[q * 4], o[q * 4 + 1], o[q * 4 + 2], o[q * 4 + 3]);
}

__global__ void k_token(const int* __restrict__ scatter) {
    int i = blockIdx.x * blockDim.x + threadIdx.x;
    if (i < M_OUT) g_token_of_row[scatter[i]] = i / TOPK;
}

__global__ void k_tiles(const int* __restrict__ splits) {
    if (threadIdx.x != 0 || blockIdx.x != 0) return;
    int off = 0, t = 0;
    for (int e = 0; e < NEXP; e++) {
        int sc = splits[e];
        for (int m0 = 0; m0 < sc; m0 += TILE_M) {
            g_tile_expert[t] = e;
            g_tile_row0[t]   = off + m0;
            int rr = sc - m0;
            g_tile_rows[t]   = rr < TILE_M ? rr : TILE_M;
            t++;
        }
        off += sc;
    }
    g_num_tiles = t;
}

// ---------------- main grouped-GEMM kernel -----------------------------------
// 128 threads = 4 warps, warp grid 2x2, warp tile 64x64. 2 CTAs/SM.
__global__ void __launch_bounds__(THREADS, 2) moe_gemm_kernel(float* __restrict__ out) {
    extern __shared__ char smem[];
    const uint32_t sbase = smem_to_u32(smem);

    const int row_tile = blockIdx.x;
    if (row_tile >= g_num_tiles) return;
    const int e    = g_tile_expert[row_tile];
    const int row0 = g_tile_row0[row_tile];
    const int rows = g_tile_rows[row_tile];
    const int n0   = blockIdx.y * TILE_N;

    const int tid  = threadIdx.x;
    const int wid  = tid >> 5;
    const int lane = tid & 31;
    const int lr = lane >> 2;         // 0..7  fragment row
    const int lc = lane & 3;          // 0..3  fragment col group
    const int wm = (wid >> 1) * 64;   // warp M offset
    const int wn = (wid & 1) * 64;    // warp N offset

    int* s_tok = reinterpret_cast<int*>(smem + SM_TOK);
    if (tid < TILE_M) {
        int r = (tid < rows) ? (row0 + tid) : row0;
        s_tok[tid] = g_token_of_row[r];
    }
    __syncthreads();

    // ---- cp.async plan: 16 rows per pass, 8 passes each for A and B ----
    const int seg   = tid & 7;          // 16B piece of the 128B row-chunk
    const int rbase = tid >> 3;         // 0..15
    uint32_t a_src[8];                  // token-dependent global offsets (floats)
#pragma unroll
    for (int j = 0; j < 8; j++)
        a_src[j] = (uint32_t)s_tok[rbase + 16 * j] * KDIM + seg * 4;
    const uint32_t b_src0 = ((uint32_t)e * NDIM + n0 + rbase) * KDIM + seg * 4;
    const uint32_t d0 = (uint32_t)rbase * (A_STRIDE * 4) + seg * 16;

    auto load_stage = [&](int ch, int s) {
        const uint32_t abase = sbase + SM_STAGE0 + s * STAGE_BYTES;
        const uint32_t bbase = abase + A_STAGE_BYTES;
        const uint32_t koff = (uint32_t)ch * CHUNK_K;
#pragma unroll
        for (int j = 0; j < 8; j++)
            CP_ASYNC16(abase + d0 + j * (16 * A_STRIDE * 4), g_xt + a_src[j] + koff);
#pragma unroll
        for (int j = 0; j < 8; j++)
            CP_ASYNC16(bbase + d0 + j * (16 * B_STRIDE * 4),
                       g_wt + b_src0 + j * (16 * KDIM) + koff);
    };

    // ---- accumulators: warp tile 64x64 -> 4 mf x 8 nf x 4 regs = 128 ----
    float acc[4][8][4];
#pragma unroll
    for (int mf = 0; mf < 4; mf++)
#pragma unroll
        for (int nf = 0; nf < 8; nf++)
#pragma unroll
            for (int r = 0; r < 4; r++) acc[mf][nf][r] = 0.f;

    load_stage(0, 0); CP_COMMIT();
    load_stage(1, 1); CP_COMMIT();

    const float* As0 = reinterpret_cast<const float*>(smem + SM_STAGE0);

#pragma unroll 1
    for (int ch = 0; ch < NUM_CHUNKS; ch++) {
        CP_WAIT_1();
        __syncthreads();

        if (ch + 2 < NUM_CHUNKS) load_stage(ch + 2, (ch + 2) % STAGES);
        CP_COMMIT();

        const int s = ch % STAGES;
        const float* As = As0 + (size_t)s * (STAGE_BYTES / 4);
        const float* Bs = As + (A_STAGE_BYTES / 4);

        // kf pairs: one LDS.128 per row covers kf=2kp (x,y) and kf=2kp+1 (z,w)
#pragma unroll
        for (int kp = 0; kp < 2; kp++) {
            const int fo = lc * 8 + kp * 4;      // float offset within packed row
            uint4 qa[4][2];
#pragma unroll
            for (int mf = 0; mf < 4; mf++) {
                const int r = wm + mf * 16 + lr;
                qa[mf][0] = *reinterpret_cast<const uint4*>(As + r * A_STRIDE + fo);
                qa[mf][1] = *reinterpret_cast<const uint4*>(As + (r + 8) * A_STRIDE + fo);
            }
            uint4 qb[8];
#pragma unroll
            for (int nf = 0; nf < 8; nf++)
                qb[nf] = *reinterpret_cast<const uint4*>(Bs + (wn + nf * 8 + lr) * B_STRIDE + fo);

            // kf = 2kp (use .x/.y), then kf = 2kp+1 (use .z/.w): 32 independent
            // MMAs between reuses of any accumulator.
#pragma unroll
            for (int mf = 0; mf < 4; mf++)
#pragma unroll
                for (int nf = 0; nf < 8; nf++)
                    mma_tf32(acc[mf][nf], qa[mf][0].x, qa[mf][1].x, qa[mf][0].y, qa[mf][1].y,
                             qb[nf].x, qb[nf].y);
#pragma unroll
            for (int mf = 0; mf < 4; mf++)
#pragma unroll
                for (int nf = 0; nf < 8; nf++)
                    mma_tf32(acc[mf][nf], qa[mf][0].z, qa[mf][1].z, qa[mf][0].w, qa[mf][1].w,
                             qb[nf].z, qb[nf].w);
        }
    }

    // ---- epilogue: direct float2 stores, mask rows beyond this tile ----
#pragma unroll
    for (int mf = 0; mf < 4; mf++) {
        const int r_lo = wm + mf * 16 + lr;
        const int r_hi = r_lo + 8;
        const bool v_lo = (r_lo < rows);
        const bool v_hi = (r_hi < rows);
        float* o_lo = out + (size_t)(row0 + r_lo) * NDIM + n0;
        float* o_hi = out + (size_t)(row0 + r_hi) * NDIM + n0;
#pragma unroll
        for (int nf = 0; nf < 8; nf++) {
            const int col = wn + nf * 8 + 2 * lc;
            if (v_lo) *reinterpret_cast<float2*>(o_lo + col) =
                make_float2(acc[mf][nf][0], acc[mf][nf][1]);
            if (v_hi) *reinterpret_cast<float2*>(o_hi + col) =
                make_float2(acc[mf][nf][2], acc[mf][nf][3]);
        }
    }
}

// ---------------- launch ------------------------------------------------------
extern "C" void kernel_launch(void* const* d_in, const int* in_sizes, int n_in,
                              void* d_out, int out_size) {
    const float* x       = (const float*)d_in[0];
    const float* w       = (const float*)d_in[1];
    const int*   scatter = (const int*)d_in[2];
    const int*   splits  = (const int*)d_in[3];
    float*       out     = (float*)d_out;
    (void)in_sizes; (void)n_in; (void)out_size;

    cudaFuncSetAttribute(moe_gemm_kernel, cudaFuncAttributeMaxDynamicSharedMemorySize, SMEM_ALLOC);

    const size_t total_chunks = ((size_t)NTOKENS * KDIM + (size_t)NEXP * NDIM * KDIM) / 32;
    k_round<<<(int)((total_chunks + 255) / 256), 256>>>(x, w);
    k_token<<<(M_OUT + 255) / 256, 256>>>(scatter);
    k_tiles<<<1, 32>>>(splits);

    dim3 grid(MAX_ROW_TILES, N_TILES);
    moe_gemm_kernel<<<grid, THREADS, SMEM_ALLOC>>>(out);
}